// round 1
// baseline (speedup 1.0000x reference)
#include <cuda_runtime.h>
#include <math.h>

#define Bb 4
#define Tt 1024
#define Dd 1024
#define Hh 16
#define HDh 64
#define LR 64
#define BT (Bb*Tt)             /* 4096 */
#define BTD (BT*Dd)            /* 4194304 */
#define STATE (Bb*Hh*HDh*HDh)  /* 262144 */

// ---------------- scratch (device globals; no allocation allowed) ----------
__device__ float g_dx[BTD];
__device__ float g_lerpx[BTD];
__device__ float g_in[5ll*BTD];      // mixed inputs for r,k,v,g,d
__device__ float g_t1[5ll*BT*LR];    // tanh(lerpx @ a.T) for 5 loras
__device__ float g_t2[BT*LR];        // tanh(in_d @ d_la.T)
__device__ float g_w[BTD];
__device__ float g_r[BTD];
__device__ float g_k[BTD];
__device__ float g_v[BTD];
__device__ float g_g[BTD];
__device__ float g_y[BTD];
__device__ float g_opre[BTD];
__device__ float g_stfb[STATE];      // fallback state sink if out buf too small

// ---------------- kernels --------------------------------------------------

// dx = x[t-1]-x[t] (x[-1]=0), lerpx = x + dx*xw
__global__ void __launch_bounds__(256) premix_kernel(
        const float* __restrict__ x, const float* __restrict__ xw,
        float* __restrict__ dx, float* __restrict__ lerpx) {
    long idx = (long)blockIdx.x * 256 + threadIdx.x;
    int dd = (int)(idx % Dd);
    long bt = idx / Dd;
    int t = (int)(bt % Tt);
    float xv = x[idx];
    float xp = (t > 0) ? x[idx - Dd] : 0.f;
    float d = xp - xv;
    dx[idx] = d;
    lerpx[idx] = fmaf(d, xw[dd], xv);
}

// C[M,N] = act( A[M,K] @ W[N,K]^T ), 64x64 tile, BK=16, 256 thr, 4x4 micro.
__global__ void __launch_bounds__(256) gemm_nt(
        const float* __restrict__ A, const float* __restrict__ W,
        float* __restrict__ C, int M, int N, int K, int act) {
    __shared__ __align__(16) float As[16][68];
    __shared__ __align__(16) float Ws[16][68];
    const int tid = threadIdx.x;
    const int bm = blockIdx.y * 64;
    const int bn = blockIdx.x * 64;
    const int lr = tid >> 2;          // 0..63
    const int lk = (tid & 3) << 2;    // 0,4,8,12
    const int tm = (tid >> 4) << 2;   // 0..60
    const int tn = (tid & 15) << 2;   // 0..60
    const float* Ap = A + (long)(bm + lr) * K + lk;
    const float* Wp = W + (long)(bn + lr) * K + lk;
    float c[4][4] = {};
    for (int k0 = 0; k0 < K; k0 += 16) {
        float4 av = *(const float4*)(Ap + k0);
        float4 wv = *(const float4*)(Wp + k0);
        As[lk+0][lr] = av.x; As[lk+1][lr] = av.y;
        As[lk+2][lr] = av.z; As[lk+3][lr] = av.w;
        Ws[lk+0][lr] = wv.x; Ws[lk+1][lr] = wv.y;
        Ws[lk+2][lr] = wv.z; Ws[lk+3][lr] = wv.w;
        __syncthreads();
        #pragma unroll
        for (int kk = 0; kk < 16; kk++) {
            float4 a = *(const float4*)&As[kk][tm];
            float4 b = *(const float4*)&Ws[kk][tn];
            float a4[4] = {a.x, a.y, a.z, a.w};
            float b4[4] = {b.x, b.y, b.z, b.w};
            #pragma unroll
            for (int ii = 0; ii < 4; ii++)
                #pragma unroll
                for (int jj = 0; jj < 4; jj++)
                    c[ii][jj] = fmaf(a4[ii], b4[jj], c[ii][jj]);
        }
        __syncthreads();
    }
    #pragma unroll
    for (int ii = 0; ii < 4; ii++) {
        #pragma unroll
        for (int jj = 0; jj < 4; jj++) {
            float v = c[ii][jj];
            if (act) v = tanhf(v);
            C[(long)(bm + tm + ii) * N + (bn + tn + jj)] = v;
        }
    }
}

// mix = l + t1 @ b^T  then  mode0: out = x + dx*mix ; mode1: out = exp(-exp(mix))
// 8 rows per block to amortize bmat traffic.
__global__ void __launch_bounds__(256) lora2_kernel(
        const float* __restrict__ t1, const float* __restrict__ bmat,
        const float* __restrict__ l, const float* __restrict__ x,
        const float* __restrict__ dx, float* __restrict__ out, int mode) {
    int row0 = blockIdx.x * 8;
    int tid = threadIdx.x;
    __shared__ float sh[8][64];
    for (int i = tid; i < 8 * 64; i += 256)
        sh[i >> 6][i & 63] = t1[(long)(row0 + (i >> 6)) * LR + (i & 63)];
    __syncthreads();
    for (int n = tid; n < Dd; n += 256) {
        float lv = l[n];
        float acc[8];
        #pragma unroll
        for (int rr = 0; rr < 8; rr++) acc[rr] = lv;
        const float4* bp = (const float4*)(bmat + (long)n * LR);
        #pragma unroll
        for (int p4 = 0; p4 < 16; p4++) {
            float4 bv = bp[p4];
            #pragma unroll
            for (int rr = 0; rr < 8; rr++) {
                acc[rr] = fmaf(sh[rr][p4*4+0], bv.x, acc[rr]);
                acc[rr] = fmaf(sh[rr][p4*4+1], bv.y, acc[rr]);
                acc[rr] = fmaf(sh[rr][p4*4+2], bv.z, acc[rr]);
                acc[rr] = fmaf(sh[rr][p4*4+3], bv.w, acc[rr]);
            }
        }
        #pragma unroll
        for (int rr = 0; rr < 8; rr++) {
            long idx = (long)(row0 + rr) * Dd + n;
            if (mode)
                out[idx] = expf(-expf(acc[rr]));
            else
                out[idx] = fmaf(dx[idx], acc[rr], x[idx]);
        }
    }
}

// Sequential state scan. One CTA per (b,h). 256 thr: j = tid&63 value column,
// gi = tid>>6 group of 16 key rows. State S[i][j] in registers.
__global__ void __launch_bounds__(256) scan_kernel(
        const float* __restrict__ r, const float* __restrict__ w,
        const float* __restrict__ k, const float* __restrict__ v,
        const float* __restrict__ init_state, const float* __restrict__ u,
        float* __restrict__ y, float* __restrict__ state_out) {
    int bh = blockIdx.x;
    int b = bh / Hh, h = bh % Hh;
    int tid = threadIdx.x;
    int j = tid & 63;
    int gi = tid >> 6;           // 0..3
    __shared__ float sh[4][64];  // r,w,k,v for current t
    __shared__ float ypart[2][4][64];
    float S[16], uu[16];
    #pragma unroll
    for (int ii = 0; ii < 16; ii++) {
        int i = gi * 16 + ii;
        S[ii] = init_state[(long)(h * 64 + i) * 64 + j];
        uu[ii] = u[h * 64 + i];
    }
    long base = (long)b * Tt * Dd + (long)h * 64;
    const float* srcs[4] = {r, w, k, v};
    const float* myp = srcs[gi] + base + j;
    float pref = myp[0];
    for (int t = 0; t < Tt; t++) {
        sh[gi][j] = pref;
        __syncthreads();
        if (t + 1 < Tt) pref = myp[(long)(t + 1) * Dd];
        float vj = sh[3][j];
        float acc = 0.f;
        #pragma unroll
        for (int ii = 0; ii < 16; ii++) {
            int i = gi * 16 + ii;
            float kv = sh[2][i] * vj;
            acc = fmaf(sh[0][i], fmaf(uu[ii], kv, S[ii]), acc);
            S[ii] = fmaf(sh[1][i], S[ii], kv);
        }
        ypart[t & 1][gi][j] = acc;
        __syncthreads();
        if (gi == 0) {
            float yy = ypart[t & 1][0][j] + ypart[t & 1][1][j]
                     + ypart[t & 1][2][j] + ypart[t & 1][3][j];
            y[base + (long)t * Dd + j] = yy;
        }
    }
    #pragma unroll
    for (int ii = 0; ii < 16; ii++) {
        int i = gi * 16 + ii;
        state_out[(long)((b * Hh + h) * 64 + i) * 64 + j] = S[ii];
    }
}

// per-(b,t,h) LayerNorm over 64 + silu(g) gating. One warp per group.
__global__ void __launch_bounds__(256) gn_gate_kernel(
        const float* __restrict__ y, const float* __restrict__ g,
        const float* __restrict__ lnw, const float* __restrict__ lnb,
        float* __restrict__ out) {
    long warp = ((long)blockIdx.x * blockDim.x + threadIdx.x) >> 5;
    int lane = threadIdx.x & 31;
    if (warp >= (long)Bb * Tt * Hh) return;
    const float* yp = y + warp * 64;
    float v0 = yp[lane], v1 = yp[lane + 32];
    float s = v0 + v1;
    #pragma unroll
    for (int off = 16; off > 0; off >>= 1) s += __shfl_xor_sync(0xffffffffu, s, off);
    float mean = s * (1.f / 64.f);
    float d0 = v0 - mean, d1 = v1 - mean;
    float vs = d0 * d0 + d1 * d1;
    #pragma unroll
    for (int off = 16; off > 0; off >>= 1) vs += __shfl_xor_sync(0xffffffffu, vs, off);
    float inv = rsqrtf(vs * (1.f / 64.f) + 1e-5f);
    float n0 = fmaf(d0 * inv, lnw[lane], lnb[lane]);
    float n1 = fmaf(d1 * inv, lnw[lane + 32], lnb[lane + 32]);
    float g0 = g[warp * 64 + lane];
    float g1 = g[warp * 64 + lane + 32];
    float s0 = g0 / (1.f + expf(-g0));
    float s1 = g1 / (1.f + expf(-g1));
    out[warp * 64 + lane] = s0 * n0;
    out[warp * 64 + lane + 32] = s1 * n1;
}

// ---------------- host -----------------------------------------------------
static float* symaddr(const void* s) {
    void* p = nullptr;
    cudaGetSymbolAddress(&p, s);
    return (float*)p;
}

extern "C" void kernel_launch(void* const* d_in, const int* in_sizes, int n_in,
                              void* d_out, int out_size) {
    (void)in_sizes; (void)n_in;
    const float* x    = (const float*)d_in[0];
    const float* xw   = (const float*)d_in[1];
    const float* rW   = (const float*)d_in[2];
    const float* kW   = (const float*)d_in[3];
    const float* vW   = (const float*)d_in[4];
    const float* gW   = (const float*)d_in[5];
    const float* la[5] = {(const float*)d_in[6],  (const float*)d_in[9],
                          (const float*)d_in[12], (const float*)d_in[15],
                          (const float*)d_in[18]};
    const float* lb[5] = {(const float*)d_in[7],  (const float*)d_in[10],
                          (const float*)d_in[13], (const float*)d_in[16],
                          (const float*)d_in[19]};
    const float* ll[5] = {(const float*)d_in[8],  (const float*)d_in[11],
                          (const float*)d_in[14], (const float*)d_in[17],
                          (const float*)d_in[20]};
    const float* ln_w = (const float*)d_in[21];
    const float* ln_b = (const float*)d_in[22];
    const float* oW   = (const float*)d_in[23];
    const float* init_state = (const float*)d_in[24];
    const float* u    = (const float*)d_in[25];

    float* out = (float*)d_out;

    float* p_dx    = symaddr(g_dx);
    float* p_lerpx = symaddr(g_lerpx);
    float* p_in    = symaddr(g_in);
    float* p_t1    = symaddr(g_t1);
    float* p_t2    = symaddr(g_t2);
    float* p_w     = symaddr(g_w);
    float* p_r     = symaddr(g_r);
    float* p_k     = symaddr(g_k);
    float* p_v     = symaddr(g_v);
    float* p_g     = symaddr(g_g);
    float* p_y     = symaddr(g_y);
    float* p_opre  = symaddr(g_opre);
    float* p_stfb  = symaddr(g_stfb);

    // 1. token shift + lerp
    premix_kernel<<<BTD / 256, 256>>>(x, xw, p_dx, p_lerpx);

    // 2. lora stage 1 for r,k,v,g,d: t1 = tanh(lerpx @ a^T)
    for (int p = 0; p < 5; p++)
        gemm_nt<<<dim3(1, BT / 64), 256>>>(p_lerpx, la[p],
                                           p_t1 + (long)p * BT * LR,
                                           BT, LR, Dd, 1);
    // 3. lora stage 2 + token mix: in_p = x + dx*(l + t1 @ b^T)
    for (int p = 0; p < 5; p++)
        lora2_kernel<<<BT / 8, 256>>>(p_t1 + (long)p * BT * LR, lb[p], ll[p],
                                      x, p_dx, p_in + (long)p * BTD, 0);

    // 4. second d-lora on in_d, then w = exp(-exp(.))
    gemm_nt<<<dim3(1, BT / 64), 256>>>(p_in + 4ll * BTD, la[4], p_t2,
                                       BT, LR, Dd, 1);
    lora2_kernel<<<BT / 8, 256>>>(p_t2, lb[4], ll[4], x, p_dx, p_w, 1);

    // 5. big projections
    gemm_nt<<<dim3(16, 64), 256>>>(p_in + 0ll * BTD, rW, p_r, BT, Dd, Dd, 0);
    gemm_nt<<<dim3(16, 64), 256>>>(p_in + 1ll * BTD, kW, p_k, BT, Dd, Dd, 0);
    gemm_nt<<<dim3(16, 64), 256>>>(p_in + 2ll * BTD, vW, p_v, BT, Dd, Dd, 0);
    gemm_nt<<<dim3(16, 64), 256>>>(p_in + 3ll * BTD, gW, p_g, BT, Dd, Dd, 0);

    // 6. recurrent scan
    float* st_out = (out_size >= BTD + STATE) ? (out + BTD) : p_stfb;
    scan_kernel<<<Bb * Hh, 256>>>(p_r, p_w, p_k, p_v, init_state, u, p_y, st_out);

    // 7. groupnorm + silu gate
    gn_gate_kernel<<<(Bb * Tt * Hh) / 8, 256>>>(p_y, p_g, ln_w, ln_b, p_opre);

    // 8. output projection into d_out
    gemm_nt<<<dim3(16, 64), 256>>>(p_opre, oW, out, BT, Dd, Dd, 0);
}

// round 2
// speedup vs baseline: 1.2391x; 1.2391x over previous
#include <cuda_runtime.h>
#include <math.h>
#include <mma.h>

#define Bb 4
#define Tt 1024
#define Dd 1024
#define Hh 16
#define HDh 64
#define LR 64
#define BT (Bb*Tt)             /* 4096 */
#define BTD (BT*Dd)            /* 4194304 */
#define STATE (Bb*Hh*HDh*HDh)  /* 262144 */

// ---------------- scratch (device globals; no allocation allowed) ----------
__device__ float g_dx[BTD];
__device__ float g_lerpx[BTD];
__device__ float g_in[5ll*BTD];      // mixed inputs for r,k,v,g,d
__device__ float g_t1[(long)BT*5*LR];// tanh(lerpx @ a.T), packed [BT, 320]
__device__ float g_t2[BT*LR];        // tanh(in_d @ d_la.T)
__device__ float g_laP[5*LR*Dd];     // packed la matrices [320, 1024]
__device__ float g_w[BTD];
__device__ float g_r[BTD];
__device__ float g_k[BTD];
__device__ float g_v[BTD];
__device__ float g_g[BTD];
__device__ float g_y[BTD];
__device__ float g_opre[BTD];
__device__ float g_stfb[STATE];      // fallback state sink if out buf too small

// ---------------- kernels --------------------------------------------------

// dx = x[t-1]-x[t] (x[-1]=0), lerpx = x + dx*xw
__global__ void __launch_bounds__(256) premix_kernel(
        const float* __restrict__ x, const float* __restrict__ xw,
        float* __restrict__ dx, float* __restrict__ lerpx) {
    long idx = (long)blockIdx.x * 256 + threadIdx.x;
    int dd = (int)(idx % Dd);
    long bt = idx / Dd;
    int t = (int)(bt % Tt);
    float xv = x[idx];
    float xp = (t > 0) ? x[idx - Dd] : 0.f;
    float d = xp - xv;
    dx[idx] = d;
    lerpx[idx] = fmaf(d, xw[dd], xv);
}

// pack 5 lora-a matrices [64,1024] into one [320,1024]
__global__ void __launch_bounds__(256) pack_la_kernel(
        const float* __restrict__ a0, const float* __restrict__ a1,
        const float* __restrict__ a2, const float* __restrict__ a3,
        const float* __restrict__ a4, float* __restrict__ dst) {
    long i = (long)blockIdx.x * 256 + threadIdx.x;
    int p = (int)(i / (LR * Dd));
    long r = i % (LR * Dd);
    const float* src = (p == 0) ? a0 : (p == 1) ? a1 : (p == 2) ? a2
                     : (p == 3) ? a3 : a4;
    dst[i] = src[r];
}

// fp32 SIMT GEMM: C[M,N] = act( A[M,K] @ W[N,K]^T ), 64x64 tile (LoRA only)
__global__ void __launch_bounds__(256) gemm_nt(
        const float* __restrict__ A, const float* __restrict__ W,
        float* __restrict__ C, int M, int N, int K, int act) {
    __shared__ __align__(16) float As[16][68];
    __shared__ __align__(16) float Ws[16][68];
    const int tid = threadIdx.x;
    const int bm = blockIdx.y * 64;
    const int bn = blockIdx.x * 64;
    const int lr = tid >> 2;
    const int lk = (tid & 3) << 2;
    const int tm = (tid >> 4) << 2;
    const int tn = (tid & 15) << 2;
    const float* Ap = A + (long)(bm + lr) * K + lk;
    const float* Wp = W + (long)(bn + lr) * K + lk;
    float c[4][4] = {};
    for (int k0 = 0; k0 < K; k0 += 16) {
        float4 av = *(const float4*)(Ap + k0);
        float4 wv = *(const float4*)(Wp + k0);
        As[lk+0][lr] = av.x; As[lk+1][lr] = av.y;
        As[lk+2][lr] = av.z; As[lk+3][lr] = av.w;
        Ws[lk+0][lr] = wv.x; Ws[lk+1][lr] = wv.y;
        Ws[lk+2][lr] = wv.z; Ws[lk+3][lr] = wv.w;
        __syncthreads();
        #pragma unroll
        for (int kk = 0; kk < 16; kk++) {
            float4 a = *(const float4*)&As[kk][tm];
            float4 b = *(const float4*)&Ws[kk][tn];
            float a4[4] = {a.x, a.y, a.z, a.w};
            float b4[4] = {b.x, b.y, b.z, b.w};
            #pragma unroll
            for (int ii = 0; ii < 4; ii++)
                #pragma unroll
                for (int jj = 0; jj < 4; jj++)
                    c[ii][jj] = fmaf(a4[ii], b4[jj], c[ii][jj]);
        }
        __syncthreads();
    }
    #pragma unroll
    for (int ii = 0; ii < 4; ii++) {
        #pragma unroll
        for (int jj = 0; jj < 4; jj++) {
            float v = c[ii][jj];
            if (act) v = tanhf(v);
            C[(long)(bm + tm + ii) * N + (bn + tn + jj)] = v;
        }
    }
}

// tf32 tensor-core GEMM: C[M,N] = A[M,K] @ W[N,K]^T.
// BM=128, BN=128, BK=16; 8 warps, each computes 32x64 (2x4 m16n16k8 frags).
#define TFLD 24
__global__ void __launch_bounds__(256) gemm_nt_tf32(
        const float* __restrict__ A, const float* __restrict__ W,
        float* __restrict__ C, int M, int N, int K) {
    using namespace nvcuda;
    __shared__ __align__(32) float As[128][TFLD];
    __shared__ __align__(32) float Bs[128][TFLD];
    const int tid = threadIdx.x;
    const int bm = blockIdx.y * 128;
    const int bn = blockIdx.x * 128;
    const int wid = tid >> 5;
    const int wy = wid >> 1;          // 0..3 : m offset wy*32
    const int wx = wid & 1;           // 0..1 : n offset wx*64
    const int r0 = tid >> 2;          // 0..63
    const int q0 = (tid & 3) << 2;    // 0,4,8,12
    const int r1 = r0 + 64;
    const float* Ap0 = A + (long)(bm + r0) * K + q0;
    const float* Ap1 = A + (long)(bm + r1) * K + q0;
    const float* Wp0 = W + (long)(bn + r0) * K + q0;
    const float* Wp1 = W + (long)(bn + r1) * K + q0;

    wmma::fragment<wmma::accumulator, 16, 16, 8, float> acc[2][4];
    #pragma unroll
    for (int i = 0; i < 2; i++)
        #pragma unroll
        for (int j = 0; j < 4; j++)
            wmma::fill_fragment(acc[i][j], 0.0f);

    float4 pa0 = *(const float4*)Ap0;
    float4 pa1 = *(const float4*)Ap1;
    float4 pb0 = *(const float4*)Wp0;
    float4 pb1 = *(const float4*)Wp1;

    for (int k0 = 0; k0 < K; k0 += 16) {
        *(float4*)&As[r0][q0] = pa0;
        *(float4*)&As[r1][q0] = pa1;
        *(float4*)&Bs[r0][q0] = pb0;
        *(float4*)&Bs[r1][q0] = pb1;
        __syncthreads();
        if (k0 + 16 < K) {
            pa0 = *(const float4*)(Ap0 + k0 + 16);
            pa1 = *(const float4*)(Ap1 + k0 + 16);
            pb0 = *(const float4*)(Wp0 + k0 + 16);
            pb1 = *(const float4*)(Wp1 + k0 + 16);
        }
        #pragma unroll
        for (int kk = 0; kk < 16; kk += 8) {
            wmma::fragment<wmma::matrix_a, 16, 16, 8,
                           wmma::precision::tf32, wmma::row_major> af[2];
            wmma::fragment<wmma::matrix_b, 16, 16, 8,
                           wmma::precision::tf32, wmma::col_major> bf[4];
            #pragma unroll
            for (int i = 0; i < 2; i++) {
                wmma::load_matrix_sync(af[i], &As[wy * 32 + i * 16][kk], TFLD);
                #pragma unroll
                for (int t = 0; t < af[i].num_elements; t++)
                    af[i].x[t] = wmma::__float_to_tf32(af[i].x[t]);
            }
            #pragma unroll
            for (int j = 0; j < 4; j++) {
                wmma::load_matrix_sync(bf[j], &Bs[wx * 64 + j * 16][kk], TFLD);
                #pragma unroll
                for (int t = 0; t < bf[j].num_elements; t++)
                    bf[j].x[t] = wmma::__float_to_tf32(bf[j].x[t]);
            }
            #pragma unroll
            for (int i = 0; i < 2; i++)
                #pragma unroll
                for (int j = 0; j < 4; j++)
                    wmma::mma_sync(acc[i][j], af[i], bf[j], acc[i][j]);
        }
        __syncthreads();
    }
    #pragma unroll
    for (int i = 0; i < 2; i++)
        #pragma unroll
        for (int j = 0; j < 4; j++)
            wmma::store_matrix_sync(
                C + (long)(bm + wy * 32 + i * 16) * N + bn + wx * 64 + j * 16,
                acc[i][j], N, wmma::mem_row_major);
}

// mix = l + t1 @ b^T  then  mode0: out = x + dx*mix ; mode1: out = exp(-exp(mix))
__global__ void __launch_bounds__(256) lora2_kernel(
        const float* __restrict__ t1, int t1_stride, int t1_off,
        const float* __restrict__ bmat,
        const float* __restrict__ l, const float* __restrict__ x,
        const float* __restrict__ dx, float* __restrict__ out, int mode) {
    int row0 = blockIdx.x * 8;
    int tid = threadIdx.x;
    __shared__ float sh[8][64];
    for (int i = tid; i < 8 * 64; i += 256)
        sh[i >> 6][i & 63] =
            t1[(long)(row0 + (i >> 6)) * t1_stride + t1_off + (i & 63)];
    __syncthreads();
    for (int n = tid; n < Dd; n += 256) {
        float lv = l[n];
        float acc[8];
        #pragma unroll
        for (int rr = 0; rr < 8; rr++) acc[rr] = lv;
        const float4* bp = (const float4*)(bmat + (long)n * LR);
        #pragma unroll
        for (int p4 = 0; p4 < 16; p4++) {
            float4 bv = bp[p4];
            #pragma unroll
            for (int rr = 0; rr < 8; rr++) {
                acc[rr] = fmaf(sh[rr][p4*4+0], bv.x, acc[rr]);
                acc[rr] = fmaf(sh[rr][p4*4+1], bv.y, acc[rr]);
                acc[rr] = fmaf(sh[rr][p4*4+2], bv.z, acc[rr]);
                acc[rr] = fmaf(sh[rr][p4*4+3], bv.w, acc[rr]);
            }
        }
        #pragma unroll
        for (int rr = 0; rr < 8; rr++) {
            long idx = (long)(row0 + rr) * Dd + n;
            if (mode)
                out[idx] = expf(-expf(acc[rr]));
            else
                out[idx] = fmaf(dx[idx], acc[rr], x[idx]);
        }
    }
}

// Sequential state scan. One CTA per (b,h).
__global__ void __launch_bounds__(256) scan_kernel(
        const float* __restrict__ r, const float* __restrict__ w,
        const float* __restrict__ k, const float* __restrict__ v,
        const float* __restrict__ init_state, const float* __restrict__ u,
        float* __restrict__ y, float* __restrict__ state_out) {
    int bh = blockIdx.x;
    int b = bh / Hh, h = bh % Hh;
    int tid = threadIdx.x;
    int j = tid & 63;
    int gi = tid >> 6;           // 0..3
    __shared__ float sh[4][64];
    __shared__ float ypart[2][4][64];
    float S[16], uu[16];
    #pragma unroll
    for (int ii = 0; ii < 16; ii++) {
        int i = gi * 16 + ii;
        S[ii] = init_state[(long)(h * 64 + i) * 64 + j];
        uu[ii] = u[h * 64 + i];
    }
    long base = (long)b * Tt * Dd + (long)h * 64;
    const float* srcs[4] = {r, w, k, v};
    const float* myp = srcs[gi] + base + j;
    float pref = myp[0];
    for (int t = 0; t < Tt; t++) {
        sh[gi][j] = pref;
        __syncthreads();
        if (t + 1 < Tt) pref = myp[(long)(t + 1) * Dd];
        float vj = sh[3][j];
        float acc = 0.f;
        #pragma unroll
        for (int ii = 0; ii < 16; ii++) {
            int i = gi * 16 + ii;
            float kv = sh[2][i] * vj;
            acc = fmaf(sh[0][i], fmaf(uu[ii], kv, S[ii]), acc);
            S[ii] = fmaf(sh[1][i], S[ii], kv);
        }
        ypart[t & 1][gi][j] = acc;
        __syncthreads();
        if (gi == 0) {
            float yy = ypart[t & 1][0][j] + ypart[t & 1][1][j]
                     + ypart[t & 1][2][j] + ypart[t & 1][3][j];
            y[base + (long)t * Dd + j] = yy;
        }
    }
    #pragma unroll
    for (int ii = 0; ii < 16; ii++) {
        int i = gi * 16 + ii;
        state_out[(long)((b * Hh + h) * 64 + i) * 64 + j] = S[ii];
    }
}

// per-(b,t,h) LayerNorm over 64 + silu(g) gating. One warp per group.
__global__ void __launch_bounds__(256) gn_gate_kernel(
        const float* __restrict__ y, const float* __restrict__ g,
        const float* __restrict__ lnw, const float* __restrict__ lnb,
        float* __restrict__ out) {
    long warp = ((long)blockIdx.x * blockDim.x + threadIdx.x) >> 5;
    int lane = threadIdx.x & 31;
    if (warp >= (long)Bb * Tt * Hh) return;
    const float* yp = y + warp * 64;
    float v0 = yp[lane], v1 = yp[lane + 32];
    float s = v0 + v1;
    #pragma unroll
    for (int off = 16; off > 0; off >>= 1) s += __shfl_xor_sync(0xffffffffu, s, off);
    float mean = s * (1.f / 64.f);
    float d0 = v0 - mean, d1 = v1 - mean;
    float vs = d0 * d0 + d1 * d1;
    #pragma unroll
    for (int off = 16; off > 0; off >>= 1) vs += __shfl_xor_sync(0xffffffffu, vs, off);
    float inv = rsqrtf(vs * (1.f / 64.f) + 1e-5f);
    float n0 = fmaf(d0 * inv, lnw[lane], lnb[lane]);
    float n1 = fmaf(d1 * inv, lnw[lane + 32], lnb[lane + 32]);
    float g0 = g[warp * 64 + lane];
    float g1 = g[warp * 64 + lane + 32];
    float s0 = g0 / (1.f + expf(-g0));
    float s1 = g1 / (1.f + expf(-g1));
    out[warp * 64 + lane] = s0 * n0;
    out[warp * 64 + lane + 32] = s1 * n1;
}

// ---------------- host -----------------------------------------------------
static float* symaddr(const void* s) {
    void* p = nullptr;
    cudaGetSymbolAddress(&p, s);
    return (float*)p;
}

extern "C" void kernel_launch(void* const* d_in, const int* in_sizes, int n_in,
                              void* d_out, int out_size) {
    (void)in_sizes; (void)n_in;
    const float* x    = (const float*)d_in[0];
    const float* xw   = (const float*)d_in[1];
    const float* rW   = (const float*)d_in[2];
    const float* kW   = (const float*)d_in[3];
    const float* vW   = (const float*)d_in[4];
    const float* gW   = (const float*)d_in[5];
    const float* la[5] = {(const float*)d_in[6],  (const float*)d_in[9],
                          (const float*)d_in[12], (const float*)d_in[15],
                          (const float*)d_in[18]};
    const float* lb[5] = {(const float*)d_in[7],  (const float*)d_in[10],
                          (const float*)d_in[13], (const float*)d_in[16],
                          (const float*)d_in[19]};
    const float* ll[5] = {(const float*)d_in[8],  (const float*)d_in[11],
                          (const float*)d_in[14], (const float*)d_in[17],
                          (const float*)d_in[20]};
    const float* ln_w = (const float*)d_in[21];
    const float* ln_b = (const float*)d_in[22];
    const float* oW   = (const float*)d_in[23];
    const float* init_state = (const float*)d_in[24];
    const float* u    = (const float*)d_in[25];

    float* out = (float*)d_out;

    float* p_dx    = symaddr(g_dx);
    float* p_lerpx = symaddr(g_lerpx);
    float* p_in    = symaddr(g_in);
    float* p_t1    = symaddr(g_t1);
    float* p_t2    = symaddr(g_t2);
    float* p_laP   = symaddr(g_laP);
    float* p_w     = symaddr(g_w);
    float* p_r     = symaddr(g_r);
    float* p_k     = symaddr(g_k);
    float* p_v     = symaddr(g_v);
    float* p_g     = symaddr(g_g);
    float* p_y     = symaddr(g_y);
    float* p_opre  = symaddr(g_opre);
    float* p_stfb  = symaddr(g_stfb);

    // 1. token shift + lerp
    premix_kernel<<<BTD / 256, 256>>>(x, xw, p_dx, p_lerpx);

    // 2. pack the 5 lora-a matrices; single fused stage-1 GEMM (N=320)
    pack_la_kernel<<<(5 * LR * Dd) / 256, 256>>>(la[0], la[1], la[2], la[3],
                                                 la[4], p_laP);
    gemm_nt<<<dim3(5, BT / 64), 256>>>(p_lerpx, p_laP, p_t1, BT, 5 * LR, Dd, 1);

    // 3. lora stage 2 + token mix: in_p = x + dx*(l + t1_p @ b^T)
    for (int p = 0; p < 5; p++)
        lora2_kernel<<<BT / 8, 256>>>(p_t1, 5 * LR, p * LR, lb[p], ll[p],
                                      x, p_dx, p_in + (long)p * BTD, 0);

    // 4. second d-lora on in_d, then w = exp(-exp(.))
    gemm_nt<<<dim3(1, BT / 64), 256>>>(p_in + 4ll * BTD, la[4], p_t2,
                                       BT, LR, Dd, 1);
    lora2_kernel<<<BT / 8, 256>>>(p_t2, LR, 0, lb[4], ll[4], x, p_dx, p_w, 1);

    // 5. big projections on tensor cores (tf32)
    gemm_nt_tf32<<<dim3(8, 32), 256>>>(p_in + 0ll * BTD, rW, p_r, BT, Dd, Dd);
    gemm_nt_tf32<<<dim3(8, 32), 256>>>(p_in + 1ll * BTD, kW, p_k, BT, Dd, Dd);
    gemm_nt_tf32<<<dim3(8, 32), 256>>>(p_in + 2ll * BTD, vW, p_v, BT, Dd, Dd);
    gemm_nt_tf32<<<dim3(8, 32), 256>>>(p_in + 3ll * BTD, gW, p_g, BT, Dd, Dd);

    // 6. recurrent scan
    float* st_out = (out_size >= BTD + STATE) ? (out + BTD) : p_stfb;
    scan_kernel<<<Bb * Hh, 256>>>(p_r, p_w, p_k, p_v, init_state, u, p_y, st_out);

    // 7. groupnorm + silu gate
    gn_gate_kernel<<<(Bb * Tt * Hh) / 8, 256>>>(p_y, p_g, ln_w, ln_b, p_opre);

    // 8. output projection on tensor cores
    gemm_nt_tf32<<<dim3(8, 32), 256>>>(p_opre, oW, out, BT, Dd, Dd);
}

// round 3
// speedup vs baseline: 1.9673x; 1.5878x over previous
#include <cuda_runtime.h>
#include <math.h>
#include <mma.h>

#define Bb 4
#define Tt 1024
#define Dd 1024
#define Hh 16
#define HDh 64
#define LR 64
#define BT (Bb*Tt)             /* 4096 */
#define BTD ((long)BT*Dd)      /* 4194304 */
#define STATE (Bb*Hh*HDh*HDh)  /* 262144 */

// ---------------- scratch (device globals; no allocation allowed) ----------
__device__ float g_dx[BTD];
__device__ float g_lerpx[BTD];
__device__ float g_in[5*BTD];        // mixed inputs for r,k,v,g,d (tf32-rounded)
__device__ float g_t1[(long)BT*384]; // tanh(lerpx @ laP^T), [BT,384] tf32
__device__ float g_t2[(long)BT*128]; // tanh(in_d @ d_la^T),  [BT,128] tf32
__device__ float g_laP[384*1024];    // packed la (tf32), rows 320..383 zero
__device__ float g_lbP[5*1024*64];   // packed lb (tf32)
__device__ float g_llP[5*1024];      // packed ll (fp32)
__device__ float g_W5[5*1024*1024];  // rW,kW,vW,gW,oW (tf32)
__device__ float g_w[BTD];
__device__ float g_proj[4*BTD];      // r,k,v,g
__device__ float g_y[BTD];
__device__ float g_opre[BTD];
__device__ float g_stfb[STATE];

__device__ __forceinline__ float rtf32(float x) {
    unsigned u;
    asm("cvt.rna.tf32.f32 %0, %1;" : "=r"(u) : "f"(x));
    return __uint_as_float(u);
}

// ---------------- elementwise / pack kernels -------------------------------

__global__ void __launch_bounds__(256) premix_kernel(
        const float* __restrict__ x, const float* __restrict__ xw,
        float* __restrict__ dx, float* __restrict__ lerpx) {
    long idx = (long)blockIdx.x * 256 + threadIdx.x;
    int dd = (int)(idx % Dd);
    long bt = idx / Dd;
    int t = (int)(bt % Tt);
    float xv = x[idx];
    float xp = (t > 0) ? x[idx - Dd] : 0.f;
    float d = xp - xv;
    dx[idx] = d;
    lerpx[idx] = rtf32(fmaf(d, xw[dd], xv));
}

__global__ void __launch_bounds__(256) pack_la_kernel(
        const float* __restrict__ a0, const float* __restrict__ a1,
        const float* __restrict__ a2, const float* __restrict__ a3,
        const float* __restrict__ a4, float* __restrict__ dst) {
    long i = (long)blockIdx.x * 256 + threadIdx.x;   // 384*1024
    int row = (int)(i >> 10);
    int col = (int)(i & 1023);
    int p = row >> 6;
    float v = 0.f;
    if (p < 5) {
        const float* src = (p == 0) ? a0 : (p == 1) ? a1 : (p == 2) ? a2
                         : (p == 3) ? a3 : a4;
        v = rtf32(src[(long)(row & 63) * 1024 + col]);
    }
    dst[i] = v;
}

__global__ void __launch_bounds__(256) pack_lb_kernel(
        const float* __restrict__ b0, const float* __restrict__ b1,
        const float* __restrict__ b2, const float* __restrict__ b3,
        const float* __restrict__ b4, float* __restrict__ dst) {
    long i = (long)blockIdx.x * 256 + threadIdx.x;   // 5*1024*64
    int p = (int)(i >> 16);
    long r = i & 65535;
    const float* src = (p == 0) ? b0 : (p == 1) ? b1 : (p == 2) ? b2
                     : (p == 3) ? b3 : b4;
    dst[i] = rtf32(src[r]);
}

__global__ void __launch_bounds__(256) pack_ll_kernel(
        const float* __restrict__ l0, const float* __restrict__ l1,
        const float* __restrict__ l2, const float* __restrict__ l3,
        const float* __restrict__ l4, float* __restrict__ dst) {
    int i = blockIdx.x * 256 + threadIdx.x;          // 5*1024
    int p = i >> 10;
    int r = i & 1023;
    const float* src = (p == 0) ? l0 : (p == 1) ? l1 : (p == 2) ? l2
                     : (p == 3) ? l3 : l4;
    dst[i] = src[r];
}

__global__ void __launch_bounds__(256) pack_w_kernel(
        const float* __restrict__ w0, const float* __restrict__ w1,
        const float* __restrict__ w2, const float* __restrict__ w3,
        const float* __restrict__ w4, float* __restrict__ dst) {
    long i = (long)blockIdx.x * 256 + threadIdx.x;   // 5*1024*1024
    int p = (int)(i >> 20);
    long r = i & 1048575;
    const float* src = (p == 0) ? w0 : (p == 1) ? w1 : (p == 2) ? w2
                     : (p == 3) ? w3 : w4;
    dst[i] = rtf32(src[r]);
}

// ---------------- tensor-core tf32 GEMM with fused epilogues ---------------
// C_tile[128,128] = A[M,K] @ W[N,K]^T   (operands pre-rounded to tf32)
// MODE 0: C = acc
// MODE 1: C = rtf32(tanh(acc))
// MODE 2: C = rtf32(x + dx*(acc + L[n]))        (N must be 1024)
// MODE 3: C = exp(-exp(acc + L[n]))
#define BKK 32
#define SLD 40
#define PIPE (2*128*SLD)          /* floats per stage (A half + B half) */
#define GSMEM (2*PIPE*4)          /* 81920 bytes */

template<int MODE>
__global__ void __launch_bounds__(256) gemm_tc(
        const float* __restrict__ A, long sAz, int lda,
        const float* __restrict__ W, long sWz, int ldw,
        float* __restrict__ C, long sCz, int ldc,
        const float* __restrict__ L, long sLz,
        const float* __restrict__ x, const float* __restrict__ dx,
        int K) {
    using namespace nvcuda;
    extern __shared__ float sm[];
    const int tid = threadIdx.x;
    const int z = blockIdx.z;
    A += (long)z * sAz;
    W += (long)z * sWz;
    C += (long)z * sCz;
    if (MODE >= 2) L += (long)z * sLz;
    const int bm = blockIdx.y * 128;
    const int bn = blockIdx.x * 128;
    const int r = tid >> 3;
    const int q = (tid & 7) * 4;
    const float* aP = A + (long)(bm + r) * lda + q;
    const float* wP = W + (long)(bn + r) * ldw + q;
    unsigned dA = (unsigned)__cvta_generic_to_shared(sm) + (r * SLD + q) * 4;
    unsigned dB = dA + 128 * SLD * 4;
    const int wid = tid >> 5;
    const int wy = wid >> 1;
    const int wx = wid & 1;

    wmma::fragment<wmma::accumulator, 16, 16, 8, float> acc[2][4];
    #pragma unroll
    for (int i = 0; i < 2; i++)
        #pragma unroll
        for (int j = 0; j < 4; j++)
            wmma::fill_fragment(acc[i][j], 0.0f);

#define ISSUE(st, k0) do {                                                   \
        unsigned _a = dA + (st) * (PIPE * 4);                                \
        unsigned _b = dB + (st) * (PIPE * 4);                                \
        _Pragma("unroll")                                                    \
        for (int _i = 0; _i < 4; _i++) {                                     \
            asm volatile("cp.async.cg.shared.global [%0], [%1], 16;\n" ::    \
                "r"(_a + _i * 32 * SLD * 4),                                 \
                "l"(aP + (long)_i * 32 * lda + (k0)));                       \
            asm volatile("cp.async.cg.shared.global [%0], [%1], 16;\n" ::    \
                "r"(_b + _i * 32 * SLD * 4),                                 \
                "l"(wP + (long)_i * 32 * ldw + (k0)));                       \
        }                                                                    \
        asm volatile("cp.async.commit_group;\n");                            \
    } while (0)

    const int nIter = K / BKK;
    ISSUE(0, 0);
    if (nIter > 1) ISSUE(1, BKK);
    asm volatile("cp.async.wait_group 1;\n");
    __syncthreads();

    for (int it = 0; it < nIter; it++) {
        int s = it & 1;
        const float* sA = sm + s * PIPE;
        const float* sB = sA + 128 * SLD;
        #pragma unroll
        for (int kk = 0; kk < BKK; kk += 8) {
            wmma::fragment<wmma::matrix_a, 16, 16, 8,
                           wmma::precision::tf32, wmma::row_major> af[2];
            wmma::fragment<wmma::matrix_b, 16, 16, 8,
                           wmma::precision::tf32, wmma::col_major> bf[4];
            #pragma unroll
            for (int i = 0; i < 2; i++)
                wmma::load_matrix_sync(af[i], sA + (wy * 32 + i * 16) * SLD + kk, SLD);
            #pragma unroll
            for (int j = 0; j < 4; j++)
                wmma::load_matrix_sync(bf[j], sB + (wx * 64 + j * 16) * SLD + kk, SLD);
            #pragma unroll
            for (int i = 0; i < 2; i++)
                #pragma unroll
                for (int j = 0; j < 4; j++)
                    wmma::mma_sync(acc[i][j], af[i], bf[j], acc[i][j]);
        }
        __syncthreads();
        if (it + 2 < nIter) {
            ISSUE(s, (it + 2) * BKK);
            asm volatile("cp.async.wait_group 1;\n");
            __syncthreads();
        } else if (it + 1 < nIter) {
            asm volatile("cp.async.wait_group 0;\n");
            __syncthreads();
        }
    }
#undef ISSUE

    if (MODE == 0 || MODE == 1) {
        #pragma unroll
        for (int i = 0; i < 2; i++)
            #pragma unroll
            for (int j = 0; j < 4; j++) {
                if (MODE == 1) {
                    #pragma unroll
                    for (int t = 0; t < 8; t++)
                        acc[i][j].x[t] = rtf32(tanhf(acc[i][j].x[t]));
                }
                wmma::store_matrix_sync(
                    C + (long)(bm + wy * 32 + i * 16) * ldc + bn + wx * 64 + j * 16,
                    acc[i][j], ldc, wmma::mem_row_major);
            }
    } else {
        __syncthreads();
        #pragma unroll
        for (int i = 0; i < 2; i++)
            #pragma unroll
            for (int j = 0; j < 4; j++)
                wmma::store_matrix_sync(
                    sm + (wy * 32 + i * 16) * 128 + wx * 64 + j * 16,
                    acc[i][j], 128, wmma::mem_row_major);
        __syncthreads();
        int row = tid >> 1;
        int c0 = (tid & 1) * 64;
        long gro = bm + row;
        #pragma unroll
        for (int i = 0; i < 16; i++) {
            int c = c0 + i * 4;
            float4 m = *(float4*)&sm[row * 128 + c];
            float4 lv = *(const float4*)&L[bn + c];
            float4 o;
            if (MODE == 2) {
                long gi = gro * 1024 + bn + c;
                float4 xv = *(const float4*)&x[gi];
                float4 dv = *(const float4*)&dx[gi];
                o.x = rtf32(fmaf(dv.x, m.x + lv.x, xv.x));
                o.y = rtf32(fmaf(dv.y, m.y + lv.y, xv.y));
                o.z = rtf32(fmaf(dv.z, m.z + lv.z, xv.z));
                o.w = rtf32(fmaf(dv.w, m.w + lv.w, xv.w));
            } else {
                o.x = expf(-expf(m.x + lv.x));
                o.y = expf(-expf(m.y + lv.y));
                o.z = expf(-expf(m.z + lv.z));
                o.w = expf(-expf(m.w + lv.w));
            }
            *(float4*)&C[gro * ldc + bn + c] = o;
        }
    }
}

// ---------------- recurrent scan -------------------------------------------
__global__ void __launch_bounds__(256) scan_kernel(
        const float* __restrict__ r, const float* __restrict__ w,
        const float* __restrict__ k, const float* __restrict__ v,
        const float* __restrict__ init_state, const float* __restrict__ u,
        float* __restrict__ y, float* __restrict__ state_out) {
    int bh = blockIdx.x;
    int b = bh / Hh, h = bh % Hh;
    int tid = threadIdx.x;
    int j = tid & 63;
    int gi = tid >> 6;
    __shared__ float sh[4][64];
    __shared__ float ypart[2][4][64];
    float S[16], uu[16];
    #pragma unroll
    for (int ii = 0; ii < 16; ii++) {
        int i = gi * 16 + ii;
        S[ii] = init_state[(long)(h * 64 + i) * 64 + j];
        uu[ii] = u[h * 64 + i];
    }
    long base = (long)b * Tt * Dd + (long)h * 64;
    const float* srcs[4] = {r, w, k, v};
    const float* myp = srcs[gi] + base + j;
    float pref = myp[0];
    for (int t = 0; t < Tt; t++) {
        sh[gi][j] = pref;
        __syncthreads();
        if (t + 1 < Tt) pref = myp[(long)(t + 1) * Dd];
        float vj = sh[3][j];
        float acc = 0.f;
        #pragma unroll
        for (int ii = 0; ii < 16; ii++) {
            int i = gi * 16 + ii;
            float kv = sh[2][i] * vj;
            acc = fmaf(sh[0][i], fmaf(uu[ii], kv, S[ii]), acc);
            S[ii] = fmaf(sh[1][i], S[ii], kv);
        }
        ypart[t & 1][gi][j] = acc;
        __syncthreads();
        if (gi == 0) {
            float yy = ypart[t & 1][0][j] + ypart[t & 1][1][j]
                     + ypart[t & 1][2][j] + ypart[t & 1][3][j];
            y[base + (long)t * Dd + j] = yy;
        }
    }
    #pragma unroll
    for (int ii = 0; ii < 16; ii++) {
        int i = gi * 16 + ii;
        state_out[(long)((b * Hh + h) * 64 + i) * 64 + j] = S[ii];
    }
}

// ---------------- groupnorm + silu gate ------------------------------------
__global__ void __launch_bounds__(256) gn_gate_kernel(
        const float* __restrict__ y, const float* __restrict__ g,
        const float* __restrict__ lnw, const float* __restrict__ lnb,
        float* __restrict__ out) {
    long warp = ((long)blockIdx.x * blockDim.x + threadIdx.x) >> 5;
    int lane = threadIdx.x & 31;
    if (warp >= (long)Bb * Tt * Hh) return;
    const float* yp = y + warp * 64;
    float v0 = yp[lane], v1 = yp[lane + 32];
    float s = v0 + v1;
    #pragma unroll
    for (int off = 16; off > 0; off >>= 1) s += __shfl_xor_sync(0xffffffffu, s, off);
    float mean = s * (1.f / 64.f);
    float d0 = v0 - mean, d1 = v1 - mean;
    float vs = d0 * d0 + d1 * d1;
    #pragma unroll
    for (int off = 16; off > 0; off >>= 1) vs += __shfl_xor_sync(0xffffffffu, vs, off);
    float inv = rsqrtf(vs * (1.f / 64.f) + 1e-5f);
    float n0 = fmaf(d0 * inv, lnw[lane], lnb[lane]);
    float n1 = fmaf(d1 * inv, lnw[lane + 32], lnb[lane + 32]);
    float g0 = g[warp * 64 + lane];
    float g1 = g[warp * 64 + lane + 32];
    float s0 = g0 / (1.f + expf(-g0));
    float s1 = g1 / (1.f + expf(-g1));
    out[warp * 64 + lane] = rtf32(s0 * n0);
    out[warp * 64 + lane + 32] = rtf32(s1 * n1);
}

// ---------------- host -----------------------------------------------------
static float* symaddr(const void* s) {
    void* p = nullptr;
    cudaGetSymbolAddress(&p, s);
    return (float*)p;
}

extern "C" void kernel_launch(void* const* d_in, const int* in_sizes, int n_in,
                              void* d_out, int out_size) {
    (void)in_sizes; (void)n_in;
    const float* x    = (const float*)d_in[0];
    const float* xw   = (const float*)d_in[1];
    const float* rW   = (const float*)d_in[2];
    const float* kW   = (const float*)d_in[3];
    const float* vW   = (const float*)d_in[4];
    const float* gW   = (const float*)d_in[5];
    const float* la[5] = {(const float*)d_in[6],  (const float*)d_in[9],
                          (const float*)d_in[12], (const float*)d_in[15],
                          (const float*)d_in[18]};
    const float* lb[5] = {(const float*)d_in[7],  (const float*)d_in[10],
                          (const float*)d_in[13], (const float*)d_in[16],
                          (const float*)d_in[19]};
    const float* ll[5] = {(const float*)d_in[8],  (const float*)d_in[11],
                          (const float*)d_in[14], (const float*)d_in[17],
                          (const float*)d_in[20]};
    const float* ln_w = (const float*)d_in[21];
    const float* ln_b = (const float*)d_in[22];
    const float* oW   = (const float*)d_in[23];
    const float* init_state = (const float*)d_in[24];
    const float* u    = (const float*)d_in[25];

    float* out = (float*)d_out;

    float* p_dx    = symaddr(g_dx);
    float* p_lerpx = symaddr(g_lerpx);
    float* p_in    = symaddr(g_in);
    float* p_t1    = symaddr(g_t1);
    float* p_t2    = symaddr(g_t2);
    float* p_laP   = symaddr(g_laP);
    float* p_lbP   = symaddr(g_lbP);
    float* p_llP   = symaddr(g_llP);
    float* p_W5    = symaddr(g_W5);
    float* p_w     = symaddr(g_w);
    float* p_proj  = symaddr(g_proj);
    float* p_y     = symaddr(g_y);
    float* p_opre  = symaddr(g_opre);
    float* p_stfb  = symaddr(g_stfb);

    static int attr_done = 0;
    if (!attr_done) {
        cudaFuncSetAttribute(gemm_tc<0>, cudaFuncAttributeMaxDynamicSharedMemorySize, GSMEM);
        cudaFuncSetAttribute(gemm_tc<1>, cudaFuncAttributeMaxDynamicSharedMemorySize, GSMEM);
        cudaFuncSetAttribute(gemm_tc<2>, cudaFuncAttributeMaxDynamicSharedMemorySize, GSMEM);
        cudaFuncSetAttribute(gemm_tc<3>, cudaFuncAttributeMaxDynamicSharedMemorySize, GSMEM);
        attr_done = 1;
    }

    // 1. token shift + lerp (lerpx rounded to tf32)
    premix_kernel<<<(int)(BTD / 256), 256>>>(x, xw, p_dx, p_lerpx);

    // 2. pack tf32 operand copies
    pack_la_kernel<<<(384 * 1024) / 256, 256>>>(la[0], la[1], la[2], la[3], la[4], p_laP);
    pack_lb_kernel<<<(5 * 1024 * 64) / 256, 256>>>(lb[0], lb[1], lb[2], lb[3], lb[4], p_lbP);
    pack_ll_kernel<<<(5 * 1024) / 256, 256>>>(ll[0], ll[1], ll[2], ll[3], ll[4], p_llP);
    pack_w_kernel<<<(5 * 1024 * 1024) / 256, 256>>>(rW, kW, vW, gW, oW, p_W5);

    // 3. lora stage 1: t1 = rtf32(tanh(lerpx @ laP^T))  [4096,384]
    gemm_tc<1><<<dim3(3, 32, 1), 256, GSMEM>>>(
        p_lerpx, 0, 1024, p_laP, 0, 1024, p_t1, 0, 384,
        nullptr, 0, nullptr, nullptr, 1024);

    // 4. fused lora stage 2 + mix for all 5 paths: in_p = rtf32(x + dx*(t1_p@b_p^T + l_p))
    gemm_tc<2><<<dim3(8, 32, 5), 256, GSMEM>>>(
        p_t1, 64, 384, p_lbP, 65536, 64, p_in, BTD, 1024,
        p_llP, 1024, x, p_dx, 64);

    // 5. second d-lora stage 1: t2 = rtf32(tanh(in_d @ d_la^T)) [4096,128] (cols 64+ are tanh(0)=0)
    gemm_tc<1><<<dim3(1, 32, 1), 256, GSMEM>>>(
        p_in + 4 * BTD, 0, 1024, p_laP + 256 * 1024, 0, 1024, p_t2, 0, 128,
        nullptr, 0, nullptr, nullptr, 1024);

    // 6. w = exp(-exp(t2 @ d_lb^T + d_ll))
    gemm_tc<3><<<dim3(8, 32, 1), 256, GSMEM>>>(
        p_t2, 0, 128, p_lbP + 4 * 65536, 0, 64, p_w, 0, 1024,
        p_llP + 4 * 1024, 0, nullptr, nullptr, 64);

    // 7. four big projections in one launch
    gemm_tc<0><<<dim3(8, 32, 4), 256, GSMEM>>>(
        p_in, BTD, 1024, p_W5, 1024 * 1024, 1024, p_proj, BTD, 1024,
        nullptr, 0, nullptr, nullptr, 1024);

    // 8. recurrent scan
    float* st_out = (out_size >= (int)(BTD + STATE)) ? (out + BTD) : p_stfb;
    scan_kernel<<<Bb * Hh, 256>>>(p_proj, p_w, p_proj + BTD, p_proj + 2 * BTD,
                                  init_state, u, p_y, st_out);

    // 9. groupnorm + silu gate (output rounded for o-proj A operand)
    gn_gate_kernel<<<(Bb * Tt * Hh) / 8, 256>>>(p_y, p_proj + 3 * BTD, ln_w, ln_b, p_opre);

    // 10. output projection
    gemm_tc<0><<<dim3(8, 32, 1), 256, GSMEM>>>(
        p_opre, 0, 1024, p_W5 + 4ll * 1024 * 1024, 0, 1024, out, 0, 1024,
        nullptr, 0, nullptr, nullptr, 1024);
}

// round 5
// speedup vs baseline: 3.1102x; 1.5809x over previous
#include <cuda_runtime.h>
#include <cuda_fp16.h>
#include <mma.h>
#include <math.h>

#define Bb 4
#define Tt 1024
#define Dd 1024
#define Hh 16
#define HDh 64
#define LR 64
#define BT (Bb*Tt)             /* 4096 */
#define BTD ((long)BT*Dd)      /* 4194304 */
#define STATE (Bb*Hh*HDh*HDh)  /* 262144 */

// ---------------- scratch (device globals; no allocation allowed) ----------
__device__ float  g_dx[BTD];
__device__ __half g_lerpx[BTD];
__device__ __half g_in[5*BTD];        // mixed inputs for r,k,v,g,d (fp16)
__device__ __half g_t1[(long)BT*384]; // tanh(lerpx @ laP^T) [BT,384]
__device__ __half g_t2[(long)BT*128]; // tanh(in_d @ d_la^T) [BT,128]
__device__ __half g_laP[384*1024];    // packed la (fp16), rows 320..383 zero
__device__ __half g_lbP[5*1024*64];   // packed lb (fp16)
__device__ float  g_llP[5*1024];      // packed ll (fp32)
__device__ __half g_W5[5ll*1024*1024];// rW,kW,vW,gW,oW (fp16)
__device__ float  g_w[BTD];
__device__ float  g_proj[4*BTD];      // r,k,v,g (fp32 for the scan)
__device__ float  g_y[BTD];
__device__ __half g_opre[BTD];
__device__ float  g_stfb[STATE];

__device__ __forceinline__ uint2 h4pack(float a, float b, float c, float d) {
    __half2 p0 = __floats2half2_rn(a, b);
    __half2 p1 = __floats2half2_rn(c, d);
    uint2 r;
    r.x = *reinterpret_cast<unsigned*>(&p0);
    r.y = *reinterpret_cast<unsigned*>(&p1);
    return r;
}

// ---------------- elementwise / pack kernels -------------------------------

__global__ void __launch_bounds__(256) premix_kernel(
        const float* __restrict__ x, const float* __restrict__ xw,
        float* __restrict__ dx, __half* __restrict__ lerpx) {
    long idx = (long)blockIdx.x * 256 + threadIdx.x;
    int dd = (int)(idx % Dd);
    long bt = idx / Dd;
    int t = (int)(bt % Tt);
    float xv = x[idx];
    float xp = (t > 0) ? x[idx - Dd] : 0.f;
    float d = xp - xv;
    dx[idx] = d;
    lerpx[idx] = __float2half_rn(fmaf(d, xw[dd], xv));
}

__global__ void __launch_bounds__(256) pack_la_kernel(
        const float* __restrict__ a0, const float* __restrict__ a1,
        const float* __restrict__ a2, const float* __restrict__ a3,
        const float* __restrict__ a4, __half* __restrict__ dst) {
    long i = (long)blockIdx.x * 256 + threadIdx.x;   // 384*1024
    int row = (int)(i >> 10);
    int col = (int)(i & 1023);
    int p = row >> 6;
    float v = 0.f;
    if (p < 5) {
        const float* src = (p == 0) ? a0 : (p == 1) ? a1 : (p == 2) ? a2
                         : (p == 3) ? a3 : a4;
        v = src[(long)(row & 63) * 1024 + col];
    }
    dst[i] = __float2half_rn(v);
}

__global__ void __launch_bounds__(256) pack_lb_kernel(
        const float* __restrict__ b0, const float* __restrict__ b1,
        const float* __restrict__ b2, const float* __restrict__ b3,
        const float* __restrict__ b4, __half* __restrict__ dst) {
    long i = (long)blockIdx.x * 256 + threadIdx.x;   // 5*1024*64
    int p = (int)(i >> 16);
    long r = i & 65535;
    const float* src = (p == 0) ? b0 : (p == 1) ? b1 : (p == 2) ? b2
                     : (p == 3) ? b3 : b4;
    dst[i] = __float2half_rn(src[r]);
}

__global__ void __launch_bounds__(256) pack_ll_kernel(
        const float* __restrict__ l0, const float* __restrict__ l1,
        const float* __restrict__ l2, const float* __restrict__ l3,
        const float* __restrict__ l4, float* __restrict__ dst) {
    int i = blockIdx.x * 256 + threadIdx.x;          // 5*1024
    int p = i >> 10;
    int r = i & 1023;
    const float* src = (p == 0) ? l0 : (p == 1) ? l1 : (p == 2) ? l2
                     : (p == 3) ? l3 : l4;
    dst[i] = src[r];
}

__global__ void __launch_bounds__(256) pack_w_kernel(
        const float* __restrict__ w0, const float* __restrict__ w1,
        const float* __restrict__ w2, const float* __restrict__ w3,
        const float* __restrict__ w4, __half* __restrict__ dst) {
    long i = (long)blockIdx.x * 256 + threadIdx.x;   // 5*1024*1024
    int p = (int)(i >> 20);
    long r = i & 1048575;
    const float* src = (p == 0) ? w0 : (p == 1) ? w1 : (p == 2) ? w2
                     : (p == 3) ? w3 : w4;
    dst[i] = __float2half_rn(src[r]);
}

// ---------------- fp16 tensor-core GEMM with fused epilogues ---------------
// tile C[128,128] = A[M,K] @ W[N,K]^T  (fp16 operands, fp32 accumulate)
// MODE 0: Cf = acc                    (float out)
// MODE 1: Ch = half(tanh(acc))        (half out)
// MODE 2: Ch = half(x + dx*(acc+L))   (half out; x/dx row length 1024)
// MODE 3: Cf = exp(-exp(acc+L))       (float out)
#define BKK 64
#define SLDH 72                      /* halves per smem row (64 + 8 pad) */
#define PIPEH (2*128*SLDH)           /* halves per stage (A + B) = 18432 */
#define GSMEM (2*PIPEH*2)            /* bytes = 73728 */

template<int MODE>
__global__ void __launch_bounds__(256) gemm_h(
        const __half* __restrict__ A, long sAz, int lda,
        const __half* __restrict__ W, long sWz, int ldw,
        void* __restrict__ Cv, long sCz, int ldc,
        const float* __restrict__ L, long sLz,
        const float* __restrict__ x, const float* __restrict__ dx,
        int K) {
    using namespace nvcuda;
    extern __shared__ __half sm[];
    const int tid = threadIdx.x;
    const int z = blockIdx.z;
    A += (long)z * sAz;
    W += (long)z * sWz;
    if (MODE >= 2) L += (long)z * sLz;
    float* Cf = (float*)Cv + (long)z * sCz;
    __half* Ch = (__half*)Cv + (long)z * sCz;
    const int bm = blockIdx.y * 128;
    const int bn = blockIdx.x * 128;
    const int r = tid >> 3;           // 0..31
    const int q = (tid & 7) * 8;      // half offset 0..56 (16B chunks)
    const __half* aP = A + (long)(bm + r) * lda + q;
    const __half* wP = W + (long)(bn + r) * ldw + q;
    unsigned dA = (unsigned)__cvta_generic_to_shared(sm) + (r * SLDH + q) * 2;
    const int wid = tid >> 5;
    const int wy = wid >> 1;          // 0..3 : m offset wy*32
    const int wx = wid & 1;           // 0..1 : n offset wx*64

    wmma::fragment<wmma::accumulator, 16, 16, 16, float> acc[2][4];
    #pragma unroll
    for (int i = 0; i < 2; i++)
        #pragma unroll
        for (int j = 0; j < 4; j++)
            wmma::fill_fragment(acc[i][j], 0.0f);

#define ISSUE(st, k0) do {                                                   \
        unsigned _a = dA + (st) * (PIPEH * 2);                               \
        unsigned _b = _a + 128 * SLDH * 2;                                   \
        _Pragma("unroll")                                                    \
        for (int _i = 0; _i < 4; _i++) {                                     \
            asm volatile("cp.async.cg.shared.global [%0], [%1], 16;\n" ::    \
                "r"(_a + _i * 32 * SLDH * 2),                                \
                "l"(aP + (long)_i * 32 * lda + (k0)));                       \
            asm volatile("cp.async.cg.shared.global [%0], [%1], 16;\n" ::    \
                "r"(_b + _i * 32 * SLDH * 2),                                \
                "l"(wP + (long)_i * 32 * ldw + (k0)));                       \
        }                                                                    \
        asm volatile("cp.async.commit_group;\n");                            \
    } while (0)

    const int nIter = K / BKK;
    ISSUE(0, 0);
    if (nIter > 1) {
        ISSUE(1, BKK);
        asm volatile("cp.async.wait_group 1;\n");
    } else {
        asm volatile("cp.async.wait_group 0;\n");
    }
    __syncthreads();

    for (int it = 0; it < nIter; it++) {
        int s = it & 1;
        const __half* sA = sm + s * PIPEH;
        const __half* sB = sA + 128 * SLDH;
        #pragma unroll
        for (int kk = 0; kk < BKK; kk += 16) {
            wmma::fragment<wmma::matrix_a, 16, 16, 16, __half, wmma::row_major> af[2];
            wmma::fragment<wmma::matrix_b, 16, 16, 16, __half, wmma::col_major> bf[4];
            #pragma unroll
            for (int i = 0; i < 2; i++)
                wmma::load_matrix_sync(af[i], sA + (wy * 32 + i * 16) * SLDH + kk, SLDH);
            #pragma unroll
            for (int j = 0; j < 4; j++)
                wmma::load_matrix_sync(bf[j], sB + (wx * 64 + j * 16) * SLDH + kk, SLDH);
            #pragma unroll
            for (int i = 0; i < 2; i++)
                #pragma unroll
                for (int j = 0; j < 4; j++)
                    wmma::mma_sync(acc[i][j], af[i], bf[j], acc[i][j]);
        }
        __syncthreads();
        if (it + 2 < nIter) {
            ISSUE(s, (it + 2) * BKK);
            asm volatile("cp.async.wait_group 1;\n");
            __syncthreads();
        } else if (it + 1 < nIter) {
            asm volatile("cp.async.wait_group 0;\n");
            __syncthreads();
        }
    }
#undef ISSUE

    if (MODE == 0) {
        #pragma unroll
        for (int i = 0; i < 2; i++)
            #pragma unroll
            for (int j = 0; j < 4; j++)
                wmma::store_matrix_sync(
                    Cf + (long)(bm + wy * 32 + i * 16) * ldc + bn + wx * 64 + j * 16,
                    acc[i][j], ldc, wmma::mem_row_major);
    } else {
        float* smf = reinterpret_cast<float*>(sm);
        __syncthreads();
        #pragma unroll
        for (int i = 0; i < 2; i++)
            #pragma unroll
            for (int j = 0; j < 4; j++)
                wmma::store_matrix_sync(
                    smf + (wy * 32 + i * 16) * 128 + wx * 64 + j * 16,
                    acc[i][j], 128, wmma::mem_row_major);
        __syncthreads();
        int row = tid >> 1;
        int c0 = (tid & 1) * 64;
        long gro = bm + row;
        #pragma unroll
        for (int i = 0; i < 16; i++) {
            int c = c0 + i * 4;
            float4 m = *(float4*)&smf[row * 128 + c];
            if (MODE == 1) {
                uint2 o = h4pack(tanhf(m.x), tanhf(m.y), tanhf(m.z), tanhf(m.w));
                *(uint2*)&Ch[gro * ldc + bn + c] = o;
            } else if (MODE == 2) {
                float4 lv = *(const float4*)&L[bn + c];
                long gi = gro * 1024 + bn + c;
                float4 xv = *(const float4*)&x[gi];
                float4 dv = *(const float4*)&dx[gi];
                uint2 o = h4pack(fmaf(dv.x, m.x + lv.x, xv.x),
                                 fmaf(dv.y, m.y + lv.y, xv.y),
                                 fmaf(dv.z, m.z + lv.z, xv.z),
                                 fmaf(dv.w, m.w + lv.w, xv.w));
                *(uint2*)&Ch[gro * ldc + bn + c] = o;
            } else {
                float4 lv = *(const float4*)&L[bn + c];
                float4 o;
                o.x = expf(-expf(m.x + lv.x));
                o.y = expf(-expf(m.y + lv.y));
                o.z = expf(-expf(m.z + lv.z));
                o.w = expf(-expf(m.w + lv.w));
                *(float4*)&Cf[gro * ldc + bn + c] = o;
            }
        }
    }
}

// ---------------- recurrent scan -------------------------------------------
__global__ void __launch_bounds__(256) scan_kernel(
        const float* __restrict__ r, const float* __restrict__ w,
        const float* __restrict__ k, const float* __restrict__ v,
        const float* __restrict__ init_state, const float* __restrict__ u,
        float* __restrict__ y, float* __restrict__ state_out) {
    int bh = blockIdx.x;
    int b = bh / Hh, h = bh % Hh;
    int tid = threadIdx.x;
    int j = tid & 63;
    int gi = tid >> 6;
    __shared__ float sh[4][64];
    __shared__ float ypart[2][4][64];
    float S[16], uu[16];
    #pragma unroll
    for (int ii = 0; ii < 16; ii++) {
        int i = gi * 16 + ii;
        S[ii] = init_state[(long)(h * 64 + i) * 64 + j];
        uu[ii] = u[h * 64 + i];
    }
    long base = (long)b * Tt * Dd + (long)h * 64;
    const float* srcs[4] = {r, w, k, v};
    const float* myp = srcs[gi] + base + j;
    float pref = myp[0];
    for (int t = 0; t < Tt; t++) {
        sh[gi][j] = pref;
        __syncthreads();
        if (t + 1 < Tt) pref = myp[(long)(t + 1) * Dd];
        float vj = sh[3][j];
        float acc = 0.f;
        #pragma unroll
        for (int ii = 0; ii < 16; ii++) {
            int i = gi * 16 + ii;
            float kv = sh[2][i] * vj;
            acc = fmaf(sh[0][i], fmaf(uu[ii], kv, S[ii]), acc);
            S[ii] = fmaf(sh[1][i], S[ii], kv);
        }
        ypart[t & 1][gi][j] = acc;
        __syncthreads();
        if (gi == 0) {
            float yy = ypart[t & 1][0][j] + ypart[t & 1][1][j]
                     + ypart[t & 1][2][j] + ypart[t & 1][3][j];
            y[base + (long)t * Dd + j] = yy;
        }
    }
    #pragma unroll
    for (int ii = 0; ii < 16; ii++) {
        int i = gi * 16 + ii;
        state_out[(long)((b * Hh + h) * 64 + i) * 64 + j] = S[ii];
    }
}

// ---------------- groupnorm + silu gate ------------------------------------
__global__ void __launch_bounds__(256) gn_gate_kernel(
        const float* __restrict__ y, const float* __restrict__ g,
        const float* __restrict__ lnw, const float* __restrict__ lnb,
        __half* __restrict__ out) {
    long warp = ((long)blockIdx.x * blockDim.x + threadIdx.x) >> 5;
    int lane = threadIdx.x & 31;
    if (warp >= (long)Bb * Tt * Hh) return;
    const float* yp = y + warp * 64;
    float v0 = yp[lane], v1 = yp[lane + 32];
    float s = v0 + v1;
    #pragma unroll
    for (int off = 16; off > 0; off >>= 1) s += __shfl_xor_sync(0xffffffffu, s, off);
    float mean = s * (1.f / 64.f);
    float d0 = v0 - mean, d1 = v1 - mean;
    float vs = d0 * d0 + d1 * d1;
    #pragma unroll
    for (int off = 16; off > 0; off >>= 1) vs += __shfl_xor_sync(0xffffffffu, vs, off);
    float inv = rsqrtf(vs * (1.f / 64.f) + 1e-5f);
    float n0 = fmaf(d0 * inv, lnw[lane], lnb[lane]);
    float n1 = fmaf(d1 * inv, lnw[lane + 32], lnb[lane + 32]);
    float g0 = g[warp * 64 + lane];
    float g1 = g[warp * 64 + lane + 32];
    float s0 = g0 / (1.f + expf(-g0));
    float s1 = g1 / (1.f + expf(-g1));
    out[warp * 64 + lane] = __float2half_rn(s0 * n0);
    out[warp * 64 + lane + 32] = __float2half_rn(s1 * n1);
}

// ---------------- host -----------------------------------------------------
static void* symaddr(const void* s) {
    void* p = nullptr;
    cudaGetSymbolAddress(&p, s);
    return p;
}

extern "C" void kernel_launch(void* const* d_in, const int* in_sizes, int n_in,
                              void* d_out, int out_size) {
    (void)in_sizes; (void)n_in;
    const float* x    = (const float*)d_in[0];
    const float* xw   = (const float*)d_in[1];
    const float* rW   = (const float*)d_in[2];
    const float* kW   = (const float*)d_in[3];
    const float* vW   = (const float*)d_in[4];
    const float* gW   = (const float*)d_in[5];
    const float* la[5] = {(const float*)d_in[6],  (const float*)d_in[9],
                          (const float*)d_in[12], (const float*)d_in[15],
                          (const float*)d_in[18]};
    const float* lb[5] = {(const float*)d_in[7],  (const float*)d_in[10],
                          (const float*)d_in[13], (const float*)d_in[16],
                          (const float*)d_in[19]};
    const float* ll[5] = {(const float*)d_in[8],  (const float*)d_in[11],
                          (const float*)d_in[14], (const float*)d_in[17],
                          (const float*)d_in[20]};
    const float* ln_w = (const float*)d_in[21];
    const float* ln_b = (const float*)d_in[22];
    const float* oW   = (const float*)d_in[23];
    const float* init_state = (const float*)d_in[24];
    const float* u    = (const float*)d_in[25];

    float* out = (float*)d_out;

    float*  p_dx    = (float*)symaddr(g_dx);
    __half* p_lerpx = (__half*)symaddr(g_lerpx);
    __half* p_in    = (__half*)symaddr(g_in);
    __half* p_t1    = (__half*)symaddr(g_t1);
    __half* p_t2    = (__half*)symaddr(g_t2);
    __half* p_laP   = (__half*)symaddr(g_laP);
    __half* p_lbP   = (__half*)symaddr(g_lbP);
    float*  p_llP   = (float*)symaddr(g_llP);
    __half* p_W5    = (__half*)symaddr(g_W5);
    float*  p_w     = (float*)symaddr(g_w);
    float*  p_proj  = (float*)symaddr(g_proj);
    float*  p_y     = (float*)symaddr(g_y);
    __half* p_opre  = (__half*)symaddr(g_opre);
    float*  p_stfb  = (float*)symaddr(g_stfb);

    static int attr_done = 0;
    if (!attr_done) {
        cudaFuncSetAttribute(gemm_h<0>, cudaFuncAttributeMaxDynamicSharedMemorySize, GSMEM);
        cudaFuncSetAttribute(gemm_h<1>, cudaFuncAttributeMaxDynamicSharedMemorySize, GSMEM);
        cudaFuncSetAttribute(gemm_h<2>, cudaFuncAttributeMaxDynamicSharedMemorySize, GSMEM);
        cudaFuncSetAttribute(gemm_h<3>, cudaFuncAttributeMaxDynamicSharedMemorySize, GSMEM);
        attr_done = 1;
    }

    // 1. token shift + lerp (lerpx in fp16)
    premix_kernel<<<(int)(BTD / 256), 256>>>(x, xw, p_dx, p_lerpx);

    // 2. pack fp16 operand copies
    pack_la_kernel<<<(384 * 1024) / 256, 256>>>(la[0], la[1], la[2], la[3], la[4], p_laP);
    pack_lb_kernel<<<(5 * 1024 * 64) / 256, 256>>>(lb[0], lb[1], lb[2], lb[3], lb[4], p_lbP);
    pack_ll_kernel<<<(5 * 1024) / 256, 256>>>(ll[0], ll[1], ll[2], ll[3], ll[4], p_llP);
    pack_w_kernel<<<(5 * 1024 * 1024) / 256, 256>>>(rW, kW, vW, gW, oW, p_W5);

    // 3. lora stage 1: t1 = half(tanh(lerpx @ laP^T))  [4096,384]
    gemm_h<1><<<dim3(3, 32, 1), 256, GSMEM>>>(
        p_lerpx, 0, 1024, p_laP, 0, 1024, p_t1, 0, 384,
        nullptr, 0, nullptr, nullptr, 1024);

    // 4. fused lora stage 2 + mix, all 5 paths: in_p = half(x + dx*(t1_p@b_p^T + l_p))
    gemm_h<2><<<dim3(8, 32, 5), 256, GSMEM>>>(
        p_t1, 64, 384, p_lbP, 65536, 64, p_in, BTD, 1024,
        p_llP, 1024, x, p_dx, 64);

    // 5. second d-lora stage 1: t2 = half(tanh(in_d @ d_la^T)) [4096,128]
    gemm_h<1><<<dim3(1, 32, 1), 256, GSMEM>>>(
        p_in + 4 * BTD, 0, 1024, p_laP + 256 * 1024, 0, 1024, p_t2, 0, 128,
        nullptr, 0, nullptr, nullptr, 1024);

    // 6. w = exp(-exp(t2 @ d_lb^T + d_ll))
    gemm_h<3><<<dim3(8, 32, 1), 256, GSMEM>>>(
        p_t2, 0, 128, p_lbP + 4 * 65536, 0, 64, p_w, 0, 1024,
        p_llP + 4 * 1024, 0, nullptr, nullptr, 64);

    // 7. four big projections in one launch (fp32 out for the scan)
    gemm_h<0><<<dim3(8, 32, 4), 256, GSMEM>>>(
        p_in, BTD, 1024, p_W5, 1024 * 1024, 1024, p_proj, BTD, 1024,
        nullptr, 0, nullptr, nullptr, 1024);

    // 8. recurrent scan
    float* st_out = (out_size >= (int)(BTD + STATE)) ? (out + BTD) : p_stfb;
    scan_kernel<<<Bb * Hh, 256>>>(p_proj, p_w, p_proj + BTD, p_proj + 2 * BTD,
                                  init_state, u, p_y, st_out);

    // 9. groupnorm + silu gate (fp16 out as o-proj A operand)
    gn_gate_kernel<<<(Bb * Tt * Hh) / 8, 256>>>(p_y, p_proj + 3 * BTD, ln_w, ln_b, p_opre);

    // 10. output projection
    gemm_h<0><<<dim3(8, 32, 1), 256, GSMEM>>>(
        p_opre, 0, 1024, p_W5 + 4ll * 1024 * 1024, 0, 1024, out, 0, 1024,
        nullptr, 0, nullptr, nullptr, 1024);
}